// round 11
// baseline (speedup 1.0000x reference)
#include <cuda_runtime.h>
#include <cuda_bf16.h>
#include <cstdint>

#define NMAX 50000
#define EMAX 800000

// ---------------- scratch (device globals: no runtime allocation) -------------
__device__ float g_hA[NMAX * 64];   // layer-0 output / layer-1 input
__device__ float g_Q[NMAX * 64];
__device__ float g_K[NMAX * 64];
__device__ float g_V[NMAX * 64];
__device__ float g_h1[NMAX * 64];
// CSR preprocessing
__device__ int   g_cnt[NMAX];       // degree, then running cursor
__device__ int   g_off2[NMAX + 1];  // exclusive prefix (CSR offsets)
__device__ int   g_psrc[EMAX];      // src node of permuted edge
__device__ int   g_pdst[EMAX];      // dst node of permuted edge
__device__ int   g_pedge[EMAX];     // permuted position -> original edge id
__device__ float g_scp[EMAX * 4];   // scores in permuted order [pos][head]

// ---------------- CSR preprocessing (once per launch) --------------------------
__global__ void prep_zero(int n) {
    int i = blockIdx.x * blockDim.x + threadIdx.x;
    if (i < n) g_cnt[i] = 0;
}

__global__ void prep_hist(const int* __restrict__ ei, int ne) {
    int e = blockIdx.x * blockDim.x + threadIdx.x;
    if (e < ne) atomicAdd(&g_cnt[ei[ne + e]], 1);
}

// single-block exclusive scan: g_cnt (deg) -> g_off2 (excl), g_cnt := excl cursor
__global__ void prep_scan(int n) {
    __shared__ int wsum[32];
    __shared__ int carry_s;
    int tid = threadIdx.x, lane = tid & 31, w = tid >> 5;
    if (tid == 0) carry_s = 0;
    __syncthreads();
    for (int base = 0; base < n; base += 1024) {
        int i = base + tid;
        int v = (i < n) ? g_cnt[i] : 0;
        int s = v;
#pragma unroll
        for (int o = 1; o < 32; o <<= 1) {
            int t = __shfl_up_sync(0xffffffffu, s, o);
            if (lane >= o) s += t;
        }
        if (lane == 31) wsum[w] = s;
        __syncthreads();
        if (w == 0) {
            int ws = wsum[lane];
#pragma unroll
            for (int o = 1; o < 32; o <<= 1) {
                int t = __shfl_up_sync(0xffffffffu, ws, o);
                if (lane >= o) ws += t;
            }
            wsum[lane] = ws;
        }
        __syncthreads();
        int pre = (w > 0) ? wsum[w - 1] : 0;
        int excl = carry_s + pre + s - v;
        if (i < n) { g_off2[i] = excl; g_cnt[i] = excl; }
        __syncthreads();
        if (tid == 0) carry_s += wsum[31];
        __syncthreads();
    }
    if (tid == 0) g_off2[n] = carry_s;
}

__global__ void prep_scatter(const int* __restrict__ ei, int ne) {
    int e = blockIdx.x * blockDim.x + threadIdx.x;
    if (e < ne) {
        int sn = ei[e];
        int d = ei[ne + e];
        int pos = atomicAdd(&g_cnt[d], 1);
        g_psrc[pos] = sn;
        g_pdst[pos] = d;
        g_pedge[pos] = e;
    }
}

// ---------------- bf16 3-term split GEMM machinery -----------------------------
__device__ __forceinline__ void split_store(uint32_t* hi, uint32_t* lo, int idx,
                                            float x, float y) {
    __nv_bfloat162 h = __floats2bfloat162_rn(x, y);
    float hx = __bfloat162float(h.x);
    float hy = __bfloat162float(h.y);
    __nv_bfloat162 l = __floats2bfloat162_rn(x - hx, y - hy);
    hi[idx] = *reinterpret_cast<uint32_t*>(&h);
    lo[idx] = *reinterpret_cast<uint32_t*>(&l);
}

__device__ __forceinline__ void mma16(float c[4], const uint32_t a[4], const uint32_t b[2]) {
    asm("mma.sync.aligned.m16n8k16.row.col.f32.bf16.bf16.f32 "
        "{%0,%1,%2,%3}, {%4,%5,%6,%7}, {%8,%9}, {%0,%1,%2,%3};"
        : "+f"(c[0]), "+f"(c[1]), "+f"(c[2]), "+f"(c[3])
        : "r"(a[0]), "r"(a[1]), "r"(a[2]), "r"(a[3]), "r"(b[0]), "r"(b[1]));
}

template<int AP, int WP>
__device__ __forceinline__ void gemm64_bf16(const uint32_t* __restrict__ Ahi,
                                            const uint32_t* __restrict__ Alo,
                                            const uint32_t* __restrict__ Whi,
                                            const uint32_t* __restrict__ Wlo,
                                            float acc[4][4], int r0, int n0) {
    int lane = threadIdx.x & 31;
    int g = lane >> 2, t4 = lane & 3;
#pragma unroll
    for (int kb = 0; kb < 32; kb += 8) {
        int ia0 = (r0 + g) * AP + kb + t4;
        int ia1 = (r0 + g + 8) * AP + kb + t4;
        uint32_t ah[4] = { Ahi[ia0], Ahi[ia1], Ahi[ia0 + 4], Ahi[ia1 + 4] };
        uint32_t al[4] = { Alo[ia0], Alo[ia1], Alo[ia0 + 4], Alo[ia1 + 4] };
#pragma unroll
        for (int nt = 0; nt < 4; ++nt) {
            int nn = n0 + nt * 8 + g;
            int ib0 = (kb + t4) * WP + nn;
            int ib1 = (kb + t4 + 4) * WP + nn;
            uint32_t bh[2] = { Whi[ib0], Whi[ib1] };
            uint32_t bl[2] = { Wlo[ib0], Wlo[ib1] };
            mma16(acc[nt], ah, bh);
            mma16(acc[nt], ah, bl);
            mma16(acc[nt], al, bh);
        }
    }
}

// smem word offsets (uint32 units)
#define A_HI 0
#define A_LO 2304      // 64*36
#define W_HI 4608
#define W_LO 6912      // + 32*72
#define SM_WORDS 9216

// ================= fused QKV GEMM =============================================
__global__ void qkvz_kernel(const float* __restrict__ A,
                            const float* __restrict__ WQ,
                            const float* __restrict__ WK,
                            const float* __restrict__ WV, int n) {
    __shared__ uint32_t sm[SM_WORDS];
    int row0 = blockIdx.x * 64;
    int tid = threadIdx.x;
    int w = tid >> 5, lane = tid & 31;
    int g = lane >> 2, t4 = lane & 3;
    int r0 = (w & 3) * 16, n0 = (w >> 2) * 32;

    for (int i = tid; i < 2048; i += 256) {
        int r = i >> 5, kp = i & 31;
        int gr = row0 + r;
        float2 v = (gr < n) ? *(const float2*)&A[(size_t)gr * 64 + kp * 2]
                            : make_float2(0.f, 0.f);
        split_store(sm + A_HI, sm + A_LO, r * 36 + kp, v.x, v.y);
    }

#pragma unroll
    for (int p = 0; p < 3; ++p) {
        const float* W = (p == 0) ? WQ : (p == 1) ? WK : WV;
        float* C = (p == 0) ? g_Q : (p == 1) ? g_K : g_V;
        __syncthreads();
        for (int i = tid; i < 2048; i += 256) {
            int kp = i >> 6, nn = i & 63;
            split_store(sm + W_HI, sm + W_LO, kp * 72 + nn,
                        W[(size_t)(2 * kp) * 64 + nn], W[(size_t)(2 * kp + 1) * 64 + nn]);
        }
        __syncthreads();

        float acc[4][4] = {};
        gemm64_bf16<36, 72>(sm + A_HI, sm + A_LO, sm + W_HI, sm + W_LO, acc, r0, n0);

#pragma unroll
        for (int nt = 0; nt < 4; ++nt) {
            int col = n0 + nt * 8 + t4 * 2;
#pragma unroll
            for (int ci = 0; ci < 2; ++ci) {
                int gr = row0 + r0 + g + 8 * ci;
                if (gr < n) {
                    float2 o = make_float2(acc[nt][ci * 2], acc[nt][ci * 2 + 1]);
                    *(float2*)&C[(size_t)gr * 64 + col] = o;
                }
            }
        }
    }
}

// ================= edge score kernel (dst-sorted order) =======================
// For permuted position range: Eh = edge_attr[pedge] @ WE; score -> g_scp[pos*4+h]
// Q[dst] gathers hit L1 (consecutive positions share dst); scp writes coalesced.
__global__ void edge_score_kernel(const float* __restrict__ Ae, const float* __restrict__ WE,
                                  int ne) {
    __shared__ uint32_t sm[SM_WORDS];
    __shared__ int s_src[64], s_dst[64], s_edge[64];
    int e0 = blockIdx.x * 64;
    int tid = threadIdx.x;
    int w = tid >> 5, lane = tid & 31;
    int g = lane >> 2, t4 = lane & 3;
    int r0 = (w & 3) * 16, n0 = (w >> 2) * 32;

    if (tid < 64) {
        int pos = e0 + tid;
        s_src[tid]  = (pos < ne) ? g_psrc[pos]  : 0;
        s_dst[tid]  = (pos < ne) ? g_pdst[pos]  : 0;
        s_edge[tid] = (pos < ne) ? g_pedge[pos] : 0;
    }
    for (int i = tid; i < 2048; i += 256) {
        int kp = i >> 6, nn = i & 63;
        split_store(sm + W_HI, sm + W_LO, kp * 72 + nn,
                    WE[(size_t)(2 * kp) * 64 + nn], WE[(size_t)(2 * kp + 1) * 64 + nn]);
    }
    __syncthreads();   // s_edge visible for the gather below
    for (int i = tid; i < 2048; i += 256) {
        int e = i >> 5, kp = i & 31;
        int pos = e0 + e;
        float2 v = (pos < ne) ? *(const float2*)&Ae[(size_t)s_edge[e] * 64 + kp * 2]
                              : make_float2(0.f, 0.f);
        split_store(sm + A_HI, sm + A_LO, e * 36 + kp, v.x, v.y);
    }
    __syncthreads();

    float acc[4][4] = {};
    gemm64_bf16<36, 72>(sm + A_HI, sm + A_LO, sm + W_HI, sm + W_LO, acc, r0, n0);
    __syncthreads();

    float* Ehs = (float*)(sm + A_HI);   // [64][68] floats
#pragma unroll
    for (int nt = 0; nt < 4; ++nt) {
        int col = n0 + nt * 8 + t4 * 2;
#pragma unroll
        for (int ci = 0; ci < 2; ++ci) {
            Ehs[(r0 + g + 8 * ci) * 68 + col]     = acc[nt][ci * 2];
            Ehs[(r0 + g + 8 * ci) * 68 + col + 1] = acc[nt][ci * 2 + 1];
        }
    }
    __syncthreads();

    // phase 2: one thread per (edge, head): score only, coalesced write at pos
    int e = tid >> 2, h = tid & 3;
    int pos = e0 + e;
    if (pos < ne) {
        int sn = s_src[e], dn = s_dst[e];
        const float4* Kp = (const float4*)(g_K + (size_t)sn * 64 + h * 16);
        const float4* Qp = (const float4*)(g_Q + (size_t)dn * 64 + h * 16);
        float s = 0.f;
#pragma unroll
        for (int i = 0; i < 4; ++i) {
            float4 k4 = Kp[i];
            float4 q4 = Qp[i];
            const float* ep = &Ehs[e * 68 + h * 16 + i * 4];
            s += k4.x * q4.x * ep[0] + k4.y * q4.y * ep[1] +
                 k4.z * q4.z * ep[2] + k4.w * q4.w * ep[3];
        }
        s *= 0.25f;                        // 1/sqrt(16)
        s = fminf(fmaxf(s, -5.f), 5.f);
        g_scp[(size_t)pos * 4 + h] = __expf(s);
    }
}

// ================= agg + attn out-proj + residual + LayerNorm1 ================
// per 64-node tile: aggregate wV/Z from CSR directly into smem A planes,
// then h1 = LN(hin + wVn @ WO + bO)
__global__ void attn_ln_kernel(const float* __restrict__ WO, const float* __restrict__ bO,
                               const float* __restrict__ g1, const float* __restrict__ be,
                               const float* __restrict__ hin, int n) {
    __shared__ uint32_t sm[SM_WORDS];
    int row0 = blockIdx.x * 64;
    int tid = threadIdx.x;
    int w = tid >> 5, lane = tid & 31;
    int g = lane >> 2, t4 = lane & 3;
    int r0 = (w & 3) * 16, n0 = (w >> 2) * 32;

    for (int i = tid; i < 2048; i += 256) {
        int kp = i >> 6, nn = i & 63;
        split_store(sm + W_HI, sm + W_LO, kp * 72 + nn,
                    WO[(size_t)(2 * kp) * 64 + nn], WO[(size_t)(2 * kp + 1) * 64 + nn]);
    }

    // aggregation: 8 warps x 8 nodes; lane covers cols [lane*2, lane*2+1], head = lane>>3
    for (int i = 0; i < 8; ++i) {
        int r = w * 8 + i;
        int gr = row0 + r;
        float ax = 0.f, ay = 0.f;
        if (gr < n) {
            int beg = g_off2[gr], end = g_off2[gr + 1];
            int h = lane >> 3;
            float z = 0.f;
            for (int p = beg; p < end; ++p) {
                int sn = g_psrc[p];                       // warp-broadcast
                float sc = g_scp[(size_t)p * 4 + h];      // L1 (4 addrs/warp)
                float2 v = *(const float2*)&g_V[(size_t)sn * 64 + lane * 2];
                ax += sc * v.x; ay += sc * v.y; z += sc;
            }
            float inv = 1.f / (z + 1e-6f);
            ax *= inv; ay *= inv;
        }
        split_store(sm + A_HI, sm + A_LO, r * 36 + lane, ax, ay);
    }
    __syncthreads();

    float acc[4][4] = {};
    gemm64_bf16<36, 72>(sm + A_HI, sm + A_LO, sm + W_HI, sm + W_LO, acc, r0, n0);
    __syncthreads();

    float* ts = (float*)(sm + A_HI);   // [64][68]
#pragma unroll
    for (int nt = 0; nt < 4; ++nt) {
        int col = n0 + nt * 8 + t4 * 2;
        float2 bb = *(const float2*)&bO[col];
#pragma unroll
        for (int ci = 0; ci < 2; ++ci) {
            int r = r0 + g + 8 * ci;
            int gr = row0 + r;
            if (gr < n) {
                float2 h4 = *(const float2*)&hin[(size_t)gr * 64 + col];
                ts[r * 68 + col]     = h4.x + acc[nt][ci * 2]     + bb.x;
                ts[r * 68 + col + 1] = h4.y + acc[nt][ci * 2 + 1] + bb.y;
            }
        }
    }
    __syncthreads();

    for (int i = 0; i < 8; ++i) {
        int r = w * 8 + i;
        int gr = row0 + r;
        if (gr >= n) break;
        float x0 = ts[r * 68 + lane], x1 = ts[r * 68 + lane + 32];
        float s = x0 + x1;
#pragma unroll
        for (int o = 16; o; o >>= 1) s += __shfl_xor_sync(0xffffffffu, s, o);
        float mu = s * (1.f / 64.f);
        float d0 = x0 - mu, d1 = x1 - mu;
        float v = d0 * d0 + d1 * d1;
#pragma unroll
        for (int o = 16; o; o >>= 1) v += __shfl_xor_sync(0xffffffffu, v, o);
        float inv = rsqrtf(v * (1.f / 64.f) + 1e-5f);
        g_h1[(size_t)gr * 64 + lane]      = d0 * inv * g1[lane] + be[lane];
        g_h1[(size_t)gr * 64 + lane + 32] = d1 * inv * g1[lane + 32] + be[lane + 32];
    }
}

// ================= fused FFN + residual + LayerNorm2 ==========================
__global__ void ffn_ln_kernel(const float* __restrict__ W1, const float* __restrict__ b1,
                              const float* __restrict__ W2, const float* __restrict__ b2,
                              const float* __restrict__ g1, const float* __restrict__ be,
                              float* __restrict__ hout, int n) {
    __shared__ uint32_t sm[13824];
    uint32_t* H_HIp = sm;
    uint32_t* H_LOp = sm + 2304;
    uint32_t* U_HIp = sm + 4608;
    uint32_t* U_LOp = sm + 6912;
    uint32_t* Wk_HI = sm + 9216;
    uint32_t* Wk_LO = sm + 11520;
    int row0 = blockIdx.x * 64;
    int tid = threadIdx.x;
    int w = tid >> 5, lane = tid & 31;
    int g = lane >> 2, t4 = lane & 3;
    int r0 = (w & 3) * 16, n0 = (w >> 2) * 32;

    for (int i = tid; i < 2048; i += 256) {
        int r = i >> 5, kp = i & 31;
        int gr = row0 + r;
        float2 v = (gr < n) ? *(const float2*)&g_h1[(size_t)gr * 64 + kp * 2]
                            : make_float2(0.f, 0.f);
        split_store(H_HIp, H_LOp, r * 36 + kp, v.x, v.y);
    }

    float acc2[4][4] = {};
#pragma unroll
    for (int kk = 0; kk < 2; ++kk) {
        __syncthreads();
        for (int i = tid; i < 2048; i += 256) {
            int kp = i >> 6, nn = i & 63;
            split_store(Wk_HI, Wk_LO, kp * 72 + nn,
                        W1[(size_t)(2 * kp) * 128 + kk * 64 + nn],
                        W1[(size_t)(2 * kp + 1) * 128 + kk * 64 + nn]);
        }
        __syncthreads();

        float acc[4][4] = {};
        gemm64_bf16<36, 72>(H_HIp, H_LOp, Wk_HI, Wk_LO, acc, r0, n0);

#pragma unroll
        for (int nt = 0; nt < 4; ++nt) {
            int col = n0 + nt * 8 + t4 * 2;
            float2 bb = *(const float2*)&b1[kk * 64 + col];
            int cp = col >> 1;
#pragma unroll
            for (int ci = 0; ci < 2; ++ci) {
                int r = r0 + g + 8 * ci;
                float u0 = fmaxf(acc[nt][ci * 2]     + bb.x, 0.f);
                float u1 = fmaxf(acc[nt][ci * 2 + 1] + bb.y, 0.f);
                split_store(U_HIp, U_LOp, r * 36 + cp, u0, u1);
            }
        }
        __syncthreads();
        for (int i = tid; i < 2048; i += 256) {
            int kp = i >> 6, nn = i & 63;
            split_store(Wk_HI, Wk_LO, kp * 72 + nn,
                        W2[(size_t)(kk * 64 + 2 * kp) * 64 + nn],
                        W2[(size_t)(kk * 64 + 2 * kp + 1) * 64 + nn]);
        }
        __syncthreads();

        gemm64_bf16<36, 72>(U_HIp, U_LOp, Wk_HI, Wk_LO, acc2, r0, n0);
    }
    __syncthreads();

    float* ts = (float*)U_HIp;   // [64][68]
#pragma unroll
    for (int nt = 0; nt < 4; ++nt) {
        int col = n0 + nt * 8 + t4 * 2;
        float2 bb = *(const float2*)&b2[col];
        int cp = col >> 1;
#pragma unroll
        for (int ci = 0; ci < 2; ++ci) {
            int r = r0 + g + 8 * ci;
            uint32_t hw = H_HIp[r * 36 + cp], lw = H_LOp[r * 36 + cp];
            __nv_bfloat162 hh = *reinterpret_cast<__nv_bfloat162*>(&hw);
            __nv_bfloat162 ll = *reinterpret_cast<__nv_bfloat162*>(&lw);
            float h0 = __bfloat162float(hh.x) + __bfloat162float(ll.x);
            float h1v = __bfloat162float(hh.y) + __bfloat162float(ll.y);
            ts[r * 68 + col]     = h0  + acc2[nt][ci * 2]     + bb.x;
            ts[r * 68 + col + 1] = h1v + acc2[nt][ci * 2 + 1] + bb.y;
        }
    }
    __syncthreads();

    for (int i = 0; i < 8; ++i) {
        int r = w * 8 + i;
        int gr = row0 + r;
        if (gr >= n) break;
        float x0 = ts[r * 68 + lane], x1 = ts[r * 68 + lane + 32];
        float s = x0 + x1;
#pragma unroll
        for (int o = 16; o; o >>= 1) s += __shfl_xor_sync(0xffffffffu, s, o);
        float mu = s * (1.f / 64.f);
        float d0 = x0 - mu, d1 = x1 - mu;
        float v = d0 * d0 + d1 * d1;
#pragma unroll
        for (int o = 16; o; o >>= 1) v += __shfl_xor_sync(0xffffffffu, v, o);
        float inv = rsqrtf(v * (1.f / 64.f) + 1e-5f);
        hout[(size_t)gr * 64 + lane]      = d0 * inv * g1[lane] + be[lane];
        hout[(size_t)gr * 64 + lane + 32] = d1 * inv * g1[lane + 32] + be[lane + 32];
    }
}

// ---------------- host orchestration ------------------------------------------
extern "C" void kernel_launch(void* const* d_in, const int* in_sizes, int n_in,
                              void* d_out, int out_size) {
    const float* x   = (const float*)d_in[0];
    const float* ea  = (const float*)d_in[1];
    const int*   ei  = (const int*)d_in[2];   // int32 per harness dtype rules
    const float* WQ  = (const float*)d_in[3];
    const float* WK  = (const float*)d_in[4];
    const float* WE  = (const float*)d_in[5];
    const float* WV  = (const float*)d_in[6];
    const float* WO  = (const float*)d_in[7];
    const float* bO  = (const float*)d_in[8];
    const float* g1  = (const float*)d_in[9];
    const float* be1 = (const float*)d_in[10];
    const float* W1  = (const float*)d_in[11];
    const float* b1  = (const float*)d_in[12];
    const float* W2  = (const float*)d_in[13];
    const float* b2  = (const float*)d_in[14];
    const float* g2  = (const float*)d_in[15];
    const float* be2 = (const float*)d_in[16];
    float* out = (float*)d_out;

    int n  = in_sizes[0] / 64;
    int ne = in_sizes[2] / 2;

    float* p_hA;
    cudaGetSymbolAddress((void**)&p_hA, g_hA);

    int nb64 = (n + 63) / 64;
    int nbe  = (ne + 63) / 64;

    // ---- CSR preprocessing (once) ----
    prep_zero<<<(n + 255) / 256, 256>>>(n);
    prep_hist<<<(ne + 255) / 256, 256>>>(ei, ne);
    prep_scan<<<1, 1024>>>(n);
    prep_scatter<<<(ne + 255) / 256, 256>>>(ei, ne);

    for (int l = 0; l < 2; ++l) {
        const float* hin  = l ? p_hA : x;
        float*       hout = l ? out : p_hA;
        size_t wo  = (size_t)l * 64 * 64;
        size_t wo1 = (size_t)l * 64 * 128;
        size_t bo  = (size_t)l * 64;
        size_t bo1 = (size_t)l * 128;

        qkvz_kernel<<<nb64, 256>>>(hin, WQ + wo, WK + wo, WV + wo, n);
        edge_score_kernel<<<nbe, 256>>>(ea, WE + wo, ne);
        attn_ln_kernel<<<nb64, 256>>>(WO + wo, bO + bo, g1 + bo, be1 + bo, hin, n);
        ffn_ln_kernel<<<nb64, 256>>>(W1 + wo1, b1 + bo1, W2 + wo1, b2 + bo,
                                     g2 + bo, be2 + bo, hout, n);
    }
}